// round 12
// baseline (speedup 1.0000x reference)
#include <cuda_runtime.h>
#include <math.h>

#define KTAP 5
#define N0 78400
#define E0 627200
#define N1 19600
#define E1 156800
#define NP2 4900
#define BATCH 100

// ---------------- scratch (static device globals; no allocation) ----------------
__device__ float d_S1[N0 * 25];        // per-dst tap scalar sums (layer 1)
__device__ float d_deg1[N0];
__device__ float d_p1[N1 * 32];
__device__ float d_y2[N1 * 1600];      // y2[n, tap(25), ch(64)]
__device__ float d_h2[N1 * 64];
__device__ float d_pool2[NP2 * 64];    // == [100, 3136] for fc1
__device__ float d_f1acc[BATCH * 512];
__device__ float d_f1[BATCH * 512];
// CSR for layer-2 edges (built per replay on side stream; input-only dependence)
__device__ int d_cnt[N1];
__device__ int d_rowstart[N1 + 1];
__device__ int d_cursor[N1];
__device__ int d_elist[E1];

__device__ __forceinline__ float elu1(float v) { return v > 0.f ? v : expm1f(v); }

// ---- packed fp32x2 helpers (Blackwell; ptxas never emits these from C++) ----
__device__ __forceinline__ unsigned long long pack2dup(float a) {
    unsigned long long r;
    asm("mov.b64 %0, {%1,%1};" : "=l"(r) : "f"(a));
    return r;
}
__device__ __forceinline__ void unpack2(unsigned long long v, float& lo, float& hi) {
    asm("mov.b64 {%0,%1}, %2;" : "=f"(lo), "=f"(hi) : "l"(v));
}
__device__ __forceinline__ void fma2(unsigned long long& d, unsigned long long a,
                                     unsigned long long b) {
    asm("fma.rn.f32x2 %0, %1, %2, %0;" : "+l"(d) : "l"(a), "l"(b));
}

// ---------------- zeroing ----------------
__global__ void zero1_kernel() {    // needed before edge1 (main stream)
    int t = blockIdx.x * blockDim.x + threadIdx.x;
    int stride = gridDim.x * blockDim.x;
    float4 z = make_float4(0.f, 0.f, 0.f, 0.f);
    float4* s1 = (float4*)d_S1;
    for (int i = t; i < N0 * 25 / 4; i += stride) s1[i] = z;
    float4* dg1 = (float4*)d_deg1;
    for (int i = t; i < N0 / 4; i += stride) dg1[i] = z;
}

__global__ void zero_csr_kernel() { // side stream: CSR counts + fc1 accumulator
    int t = blockIdx.x * blockDim.x + threadIdx.x;
    int stride = gridDim.x * blockDim.x;
    for (int i = t; i < N1; i += stride) d_cnt[i] = 0;
    float4 z = make_float4(0.f, 0.f, 0.f, 0.f);
    float4* f1 = (float4*)d_f1acc;
    for (int i = t; i < BATCH * 512 / 4; i += stride) f1[i] = z;
}

// ---------------- CSR build (side stream; depends only on ei1) ----------------
__global__ void hist2_kernel(const int* __restrict__ ei) {
    int e = blockIdx.x * 256 + threadIdx.x;
    if (e >= E1) return;
    atomicAdd(&d_cnt[__ldg(&ei[E1 + e])], 1);
}

__global__ void scan2_kernel() {   // single block, 1024 threads
    __shared__ int sdata[1024];
    __shared__ int soff;
    int tid = threadIdx.x;
    if (tid == 0) { soff = 0; d_rowstart[0] = 0; }
    __syncthreads();
    for (int base = 0; base < N1; base += 1024) {
        int v = (base + tid < N1) ? d_cnt[base + tid] : 0;
        sdata[tid] = v;
        __syncthreads();
        for (int off = 1; off < 1024; off <<= 1) {
            int t = (tid >= off) ? sdata[tid - off] : 0;
            __syncthreads();
            sdata[tid] += t;
            __syncthreads();
        }
        int incl = sdata[tid];
        if (base + tid < N1) {
            d_rowstart[base + tid + 1] = soff + incl;
            d_cursor[base + tid] = soff + incl - v;   // exclusive prefix
        }
        __syncthreads();
        if (tid == 1023) soff += sdata[1023];
        __syncthreads();
    }
}

__global__ void scatter2_kernel(const int* __restrict__ ei) {
    int e = blockIdx.x * 256 + threadIdx.x;
    if (e >= E1) return;
    int dst = __ldg(&ei[E1 + e]);
    int pos = atomicAdd(&d_cursor[dst], 1);
    d_elist[pos] = e;
}

// ---------------- layer 1 scatter: 1 thread/edge, 4 tap atomics + deg ----------------
__global__ void edge1_kernel(const float* __restrict__ x,
                             const float2* __restrict__ pseudo,
                             const int* __restrict__ ei) {
    int e = blockIdx.x * 256 + threadIdx.x;
    if (e >= E0) return;
    float2 ps = __ldg(&pseudo[e]);
    float px = ps.x * (KTAP - 1), py = ps.y * (KTAP - 1);
    float kfx = floorf(px), kfy = floorf(py);
    float fx = px - kfx, fy = py - kfy;
    int k0x = (int)kfx, k0y = (int)kfy;
    int k1x = min(k0x + 1, KTAP - 1), k1y = min(k0y + 1, KTAP - 1);
    int src = __ldg(&ei[e]);
    int dst = __ldg(&ei[E0 + e]);
    float xs = __ldg(&x[src]);
    float* Sb = d_S1 + dst * 25;
    atomicAdd(Sb + k0x * 5 + k0y, (1.f - fx) * (1.f - fy) * xs);
    atomicAdd(Sb + k0x * 5 + k1y, (1.f - fx) * fy * xs);
    atomicAdd(Sb + k1x * 5 + k0y, fx * (1.f - fy) * xs);
    atomicAdd(Sb + k1x * 5 + k1y, fx * fy * xs);
    atomicAdd(&d_deg1[dst], 1.f);
}

// ---------------- fused layer-1 node update + ELU + 2x2 maxpool ----------------
__global__ void node1pool1_kernel(const float* __restrict__ x,
                                  const float* __restrict__ W1,
                                  const float* __restrict__ root1,
                                  const float* __restrict__ b1) {
    __shared__ unsigned long long sWp[25 * 16];   // W1 as f32x2 pairs
    __shared__ unsigned long long sRp[16];
    __shared__ unsigned long long sBp[16];
    int tid = threadIdx.x;                         // 256
    const unsigned long long* W1q = (const unsigned long long*)W1;
    for (int i = tid; i < 400; i += 256) sWp[i] = W1q[i];
    if (tid < 16) sRp[tid] = ((const unsigned long long*)root1)[tid];
    else if (tid < 32) sBp[tid - 16] = ((const unsigned long long*)b1)[tid - 16];
    __syncthreads();
    int gt = blockIdx.x * 256 + tid;
    int cell = gt >> 3;
    int sub = gt & 7;                              // channel quad index
    if (cell >= N1) return;
    int b = cell / 196, rem = cell % 196;
    int r2 = rem / 14, c2 = rem % 14;
    int base = b * 784 + r2 * 56 + c2 * 2;
    const int offs[4] = {0, 1, 28, 29};
    float pv0 = -1e30f, pv1 = -1e30f, pv2 = -1e30f, pv3 = -1e30f;
    float r0, r1, r2f, r3, bb0, bb1, bb2, bb3;
    unpack2(sRp[sub * 2], r0, r1);
    unpack2(sRp[sub * 2 + 1], r2f, r3);
    unpack2(sBp[sub * 2], bb0, bb1);
    unpack2(sBp[sub * 2 + 1], bb2, bb3);
    #pragma unroll
    for (int nn = 0; nn < 4; nn++) {
        int node = base + offs[nn];
        const float* Sb = d_S1 + node * 25;
        unsigned long long a0 = 0ull, a1 = 0ull;
        #pragma unroll
        for (int t = 0; t < 25; t++) {
            unsigned long long sp = pack2dup(__ldg(Sb + t));
            fma2(a0, sp, sWp[t * 16 + sub * 2]);
            fma2(a1, sp, sWp[t * 16 + sub * 2 + 1]);
        }
        float inv = 1.f / fmaxf(__ldg(&d_deg1[node]), 1.f);
        float xv = __ldg(&x[node]);
        float v0, v1, v2, v3;
        unpack2(a0, v0, v1);
        unpack2(a1, v2, v3);
        v0 = elu1(v0 * inv + xv * r0 + bb0);
        v1 = elu1(v1 * inv + xv * r1 + bb1);
        v2 = elu1(v2 * inv + xv * r2f + bb2);
        v3 = elu1(v3 * inv + xv * r3 + bb3);
        pv0 = fmaxf(pv0, v0);
        pv1 = fmaxf(pv1, v1);
        pv2 = fmaxf(pv2, v2);
        pv3 = fmaxf(pv3, v3);
    }
    ((float4*)(d_p1 + cell * 32))[sub] = make_float4(pv0, pv1, pv2, pv3);
}

// ---------------- y2 = P1[N1,32] @ W2mat[32,1600] ----------------
__global__ __launch_bounds__(128) void gemm_y2_kernel(const float* __restrict__ W2) {
    __shared__ __align__(16) float sP[128][36];
    __shared__ __align__(16) float sW[32][64];
    int tid = threadIdx.x;             // 128
    int kk = blockIdx.x;               // tap
    int bm = blockIdx.y * 128;
    int tx = tid & 7, ty = tid >> 3;
    #pragma unroll
    for (int j = 0; j < 32; j++) {
        int i = tid + j * 128;
        int r = i >> 5, c = i & 31;
        int gm = bm + r;
        sP[r][c] = (gm < N1) ? d_p1[gm * 32 + c] : 0.f;
    }
    #pragma unroll
    for (int j = 0; j < 16; j++) {
        int i = tid + j * 128;
        ((float*)sW)[i] = W2[kk * 2048 + i];
    }
    __syncthreads();
    unsigned long long acc2[8][4];
    #pragma unroll
    for (int i = 0; i < 8; i++)
        #pragma unroll
        for (int j = 0; j < 4; j++) acc2[i][j] = 0ull;
    #pragma unroll
    for (int kc = 0; kc < 32; kc += 4) {
        float4 a4[8];
        #pragma unroll
        for (int i = 0; i < 8; i++)
            a4[i] = *reinterpret_cast<const float4*>(&sP[ty * 8 + i][kc]);
        #pragma unroll
        for (int q = 0; q < 4; q++) {
            int k = kc + q;
            ulonglong2 bv0 = *reinterpret_cast<const ulonglong2*>(&sW[k][tx * 8]);
            ulonglong2 bv1 = *reinterpret_cast<const ulonglong2*>(&sW[k][tx * 8 + 4]);
            #pragma unroll
            for (int i = 0; i < 8; i++) {
                float av = ((const float*)&a4[i])[q];
                unsigned long long ap = pack2dup(av);
                fma2(acc2[i][0], ap, bv0.x);
                fma2(acc2[i][1], ap, bv0.y);
                fma2(acc2[i][2], ap, bv1.x);
                fma2(acc2[i][3], ap, bv1.y);
            }
        }
    }
    #pragma unroll
    for (int i = 0; i < 8; i++) {
        int gm = bm + ty * 8 + i;
        if (gm < N1) {
            float v[8];
            #pragma unroll
            for (int j = 0; j < 4; j++) unpack2(acc2[i][j], v[2 * j], v[2 * j + 1]);
            float4* op = (float4*)(d_y2 + (size_t)gm * 1600 + kk * 64 + tx * 8);
            op[0] = make_float4(v[0], v[1], v[2], v[3]);
            op[1] = make_float4(v[4], v[5], v[6], v[7]);
        }
    }
}

// ---------------- fused layer-2 gather-reduce + node update + ELU (CSR) ----------------
// block = 256 threads = 16 dst nodes x 16 lanes (each lane owns a 4-ch quad)
__global__ __launch_bounds__(256) void gather2_kernel(
        const float2* __restrict__ pseudo,
        const int* __restrict__ ei,
        const float* __restrict__ root2,
        const float* __restrict__ b2) {
    __shared__ __align__(16) float sR[32][64];
    __shared__ float sP[16][33];
    int tid = threadIdx.x;
    int bn = blockIdx.x * 16;
    #pragma unroll
    for (int j = 0; j < 8; j++) {
        int i = tid + j * 256;
        ((float*)sR)[i] = root2[i];
    }
    #pragma unroll
    for (int j = 0; j < 2; j++) {
        int i = tid + j * 256;
        int r = i >> 5, c = i & 31;
        sP[r][c] = d_p1[(bn + r) * 32 + c];
    }
    __syncthreads();
    int ty = tid >> 4, sub = tid & 15;
    int n = bn + ty;
    int s = __ldg(&d_rowstart[n]);
    int cnt = __ldg(&d_rowstart[n + 1]) - s;
    float4 acc = make_float4(0.f, 0.f, 0.f, 0.f);
    for (int j = 0; j < cnt; j++) {
        int e = __ldg(&d_elist[s + j]);
        float2 ps = __ldg(&pseudo[e]);
        float px = ps.x * (KTAP - 1), py = ps.y * (KTAP - 1);
        float kfx = floorf(px), kfy = floorf(py);
        float fx = px - kfx, fy = py - kfy;
        int k0x = (int)kfx, k0y = (int)kfy;
        int k1x = min(k0x + 1, KTAP - 1), k1y = min(k0y + 1, KTAP - 1);
        float w00 = (1.f - fx) * (1.f - fy);
        float w01 = (1.f - fx) * fy;
        float w10 = fx * (1.f - fy);
        float w11 = fx * fy;
        int src = __ldg(&ei[e]);
        const float* yb = d_y2 + (size_t)src * 1600;
        float4 v0 = __ldg(&((const float4*)(yb + (k0x * 5 + k0y) * 64))[sub]);
        float4 v1 = __ldg(&((const float4*)(yb + (k0x * 5 + k1y) * 64))[sub]);
        float4 v2 = __ldg(&((const float4*)(yb + (k1x * 5 + k0y) * 64))[sub]);
        float4 v3 = __ldg(&((const float4*)(yb + (k1x * 5 + k1y) * 64))[sub]);
        acc.x += w00 * v0.x + w01 * v1.x + w10 * v2.x + w11 * v3.x;
        acc.y += w00 * v0.y + w01 * v1.y + w10 * v2.y + w11 * v3.y;
        acc.z += w00 * v0.z + w01 * v1.z + w10 * v2.z + w11 * v3.z;
        acc.w += w00 * v0.w + w01 * v1.w + w10 * v2.w + w11 * v3.w;
    }
    float inv = 1.f / fmaxf((float)cnt, 1.f);
    // root term: p1[n,:32] @ root2[:, 4-ch quad]
    unsigned long long a0 = 0ull, a1 = 0ull;
    #pragma unroll
    for (int i = 0; i < 32; i++) {
        unsigned long long ap = pack2dup(sP[ty][i]);
        ulonglong2 bv = *reinterpret_cast<const ulonglong2*>(&sR[i][sub * 4]);
        fma2(a0, ap, bv.x);
        fma2(a1, ap, bv.y);
    }
    float r0, r1, r2, r3;
    unpack2(a0, r0, r1);
    unpack2(a1, r2, r3);
    float4 bb = __ldg(&((const float4*)b2)[sub]);
    float4 o;
    o.x = elu1(acc.x * inv + r0 + bb.x);
    o.y = elu1(acc.y * inv + r1 + bb.y);
    o.z = elu1(acc.z * inv + r2 + bb.z);
    o.w = elu1(acc.w * inv + r3 + bb.w);
    *(float4*)(d_h2 + n * 64 + sub * 4) = o;
}

// ---------------- maxpool on [25,28,28,64] -> [25,14,14,64] (float4) ----------------
__global__ void pool2_kernel() {
    int idx = blockIdx.x * blockDim.x + threadIdx.x;
    if (idx >= NP2 * 16) return;
    int q = idx & 15;
    int m = idx >> 4;
    int c2 = m % 14, r2 = (m / 14) % 14, bb = m / 196;
    int base = (bb * 28 + r2 * 2) * 28 + c2 * 2;
    const float4* h = (const float4*)d_h2;
    float4 a0 = h[base * 16 + q];
    float4 a1 = h[(base + 1) * 16 + q];
    float4 a2 = h[(base + 28) * 16 + q];
    float4 a3 = h[(base + 29) * 16 + q];
    float4 r;
    r.x = fmaxf(fmaxf(a0.x, a1.x), fmaxf(a2.x, a3.x));
    r.y = fmaxf(fmaxf(a0.y, a1.y), fmaxf(a2.y, a3.y));
    r.z = fmaxf(fmaxf(a0.z, a1.z), fmaxf(a2.z, a3.z));
    r.w = fmaxf(fmaxf(a0.w, a1.w), fmaxf(a2.w, a3.w));
    ((float4*)d_pool2)[idx] = r;
}

// ---------------- fc1: [100,3136]@[3136,512], K split 4 ways, fp32x2, atomic combine ----------------
__global__ void fc1_kernel(const float* __restrict__ W) {
    __shared__ float sX[16][17];
    __shared__ __align__(16) float sW[16][64];
    int tid = threadIdx.x;
    int tx = tid & 15, ty = tid >> 4;
    int bn = blockIdx.x * 64;
    int bm = blockIdx.y * 16;
    int ks = blockIdx.z * 784;
    unsigned long long acc2[2] = {0ull, 0ull};
    for (int kc = 0; kc < 49; kc++) {
        int k0 = ks + kc * 16;
        {
            int gm = bm + ty;
            sX[ty][tx] = (gm < BATCH) ? d_pool2[gm * 3136 + k0 + tx] : 0.f;
        }
        #pragma unroll
        for (int j = 0; j < 4; j++) {
            int i = tid + j * 256;
            sW[i >> 6][i & 63] = W[(k0 + (i >> 6)) * 512 + bn + (i & 63)];
        }
        __syncthreads();
        #pragma unroll
        for (int k = 0; k < 16; k++) {
            unsigned long long ap = pack2dup(sX[ty][k]);
            ulonglong2 bv = *reinterpret_cast<const ulonglong2*>(&sW[k][tx * 4]);
            fma2(acc2[0], ap, bv.x);
            fma2(acc2[1], ap, bv.y);
        }
        __syncthreads();
    }
    int row = bm + ty;
    if (row < BATCH) {
        float a0, a1, a2, a3;
        unpack2(acc2[0], a0, a1);
        unpack2(acc2[1], a2, a3);
        float* p = &d_f1acc[row * 512 + bn + tx * 4];
        atomicAdd(p + 0, a0);
        atomicAdd(p + 1, a1);
        atomicAdd(p + 2, a2);
        atomicAdd(p + 3, a3);
    }
}

__global__ void elu_f1_kernel(const float* __restrict__ b) {
    int i = blockIdx.x * blockDim.x + threadIdx.x;
    if (i >= BATCH * 512) return;
    d_f1[i] = elu1(d_f1acc[i] + __ldg(&b[i & 511]));
}

// ---------------- fc2 + ELU + log_softmax ----------------
__global__ void fc2_kernel(const float* __restrict__ W,
                           const float* __restrict__ b,
                           float* __restrict__ out) {
    int row = blockIdx.x;
    int o = threadIdx.x >> 5;
    int lane = threadIdx.x & 31;
    float s = 0.f;
    for (int k = lane; k < 512; k += 32)
        s += d_f1[row * 512 + k] * __ldg(&W[k * 10 + o]);
    #pragma unroll
    for (int off = 16; off; off >>= 1) s += __shfl_xor_sync(0xffffffffu, s, off);
    __shared__ float vals[10];
    if (lane == 0) vals[o] = elu1(s + b[o]);
    __syncthreads();
    if (threadIdx.x == 0) {
        float mx = -1e30f;
        #pragma unroll
        for (int i = 0; i < 10; i++) mx = fmaxf(mx, vals[i]);
        float se = 0.f;
        #pragma unroll
        for (int i = 0; i < 10; i++) se += expf(vals[i] - mx);
        float lse = mx + logf(se);
        #pragma unroll
        for (int i = 0; i < 10; i++) out[row * 10 + i] = vals[i] - lse;
    }
}

extern "C" void kernel_launch(void* const* d_in, const int* in_sizes, int n_in,
                              void* d_out, int out_size) {
    const float* x        = (const float*)d_in[0];
    const float2* pseudo0 = (const float2*)d_in[1];
    const float2* pseudo1 = (const float2*)d_in[2];
    const float* W1       = (const float*)d_in[3];
    const float* root1    = (const float*)d_in[4];
    const float* b1       = (const float*)d_in[5];
    const float* W2       = (const float*)d_in[6];
    const float* root2    = (const float*)d_in[7];
    const float* b2       = (const float*)d_in[8];
    const float* fc1_w    = (const float*)d_in[9];
    const float* fc1_b    = (const float*)d_in[10];
    const float* fc2_w    = (const float*)d_in[11];
    const float* fc2_b    = (const float*)d_in[12];
    const int*   ei0      = (const int*)d_in[13];
    const int*   ei1      = (const int*)d_in[14];
    float* out = (float*)d_out;

    static cudaStream_t s2 = nullptr;
    static cudaEvent_t evFork = nullptr, evJoin = nullptr;
    if (s2 == nullptr) {
        cudaStreamCreateWithFlags(&s2, cudaStreamNonBlocking);
        cudaEventCreateWithFlags(&evFork, cudaEventDisableTiming);
        cudaEventCreateWithFlags(&evJoin, cudaEventDisableTiming);
    }

    // fork: CSR build depends only on ei1 — overlap with entire layer-1 chain
    cudaEventRecord(evFork, 0);
    cudaStreamWaitEvent(s2, evFork, 0);
    zero_csr_kernel<<<128, 256, 0, s2>>>();
    hist2_kernel<<<(E1 + 255) / 256, 256, 0, s2>>>(ei1);
    scan2_kernel<<<1, 1024, 0, s2>>>();
    scatter2_kernel<<<(E1 + 255) / 256, 256, 0, s2>>>(ei1);
    cudaEventRecord(evJoin, s2);

    zero1_kernel<<<512, 256>>>();
    edge1_kernel<<<(E0 + 255) / 256, 256>>>(x, pseudo0, ei0);
    node1pool1_kernel<<<(N1 * 8 + 255) / 256, 256>>>(x, W1, root1, b1);
    gemm_y2_kernel<<<dim3(25, (N1 + 127) / 128), 128>>>(W2);
    cudaStreamWaitEvent(0, evJoin, 0);
    gather2_kernel<<<N1 / 16, 256>>>(pseudo1, ei1, root2, b2);
    pool2_kernel<<<(NP2 * 16 + 255) / 256, 256>>>();
    fc1_kernel<<<dim3(8, 7, 4), 256>>>(fc1_w);
    elu_f1_kernel<<<(BATCH * 512 + 255) / 256, 256>>>(fc1_b);
    fc2_kernel<<<BATCH, 320>>>(fc2_w, fc2_b, out);
}

// round 13
// speedup vs baseline: 1.1733x; 1.1733x over previous
#include <cuda_runtime.h>
#include <math.h>

#define KTAP 5
#define N0 78400
#define E0 627200
#define N1 19600
#define E1 156800
#define NP2 4900
#define BATCH 100

// ---------------- scratch (static device globals; no allocation) ----------------
__device__ float d_S1[N0 * 25];        // per-dst tap scalar sums (layer 1)
__device__ float d_deg1[N0];
__device__ float d_p1[N1 * 32];
__device__ float d_y2[N1 * 1600];      // y2[n, tap(25), ch(64)]
__device__ float d_agg2[N1 * 64];
__device__ float d_deg2[N1];
__device__ float d_h2[N1 * 64];
__device__ float d_pool2[NP2 * 64];    // == [100, 3136] for fc1
__device__ float d_f1acc[BATCH * 512];
__device__ float d_f1[BATCH * 512];

__device__ __forceinline__ float elu1(float v) { return v > 0.f ? v : expm1f(v); }

__device__ __forceinline__ void red4(float* p, float4 v) {
    asm volatile("red.global.add.v4.f32 [%0], {%1,%2,%3,%4};"
                 :: "l"(p), "f"(v.x), "f"(v.y), "f"(v.z), "f"(v.w) : "memory");
}

// ---- packed fp32x2 helpers ----
__device__ __forceinline__ unsigned long long pack2dup(float a) {
    unsigned long long r;
    asm("mov.b64 %0, {%1,%1};" : "=l"(r) : "f"(a));
    return r;
}
__device__ __forceinline__ void unpack2(unsigned long long v, float& lo, float& hi) {
    asm("mov.b64 {%0,%1}, %2;" : "=f"(lo), "=f"(hi) : "l"(v));
}
__device__ __forceinline__ void fma2(unsigned long long& d, unsigned long long a,
                                     unsigned long long b) {
    asm("fma.rn.f32x2 %0, %1, %2, %0;" : "+l"(d) : "l"(a), "l"(b));
}

// ---- tf32 helpers ----
__device__ __forceinline__ unsigned int f2tf32(float f) {
    unsigned int u;
    asm("cvt.rna.tf32.f32 %0, %1;" : "=r"(u) : "f"(f));
    return u;
}
__device__ __forceinline__ void mma_tf32(float& c0, float& c1, float& c2, float& c3,
                                         unsigned int a0, unsigned int a1,
                                         unsigned int a2, unsigned int a3,
                                         unsigned int b0, unsigned int b1) {
    asm("mma.sync.aligned.m16n8k8.row.col.f32.tf32.tf32.f32 "
        "{%0,%1,%2,%3}, {%4,%5,%6,%7}, {%8,%9}, {%0,%1,%2,%3};"
        : "+f"(c0), "+f"(c1), "+f"(c2), "+f"(c3)
        : "r"(a0), "r"(a1), "r"(a2), "r"(a3), "r"(b0), "r"(b1));
}

// ---------------- zeroing (fresh every replay; ~14MB total) ----------------
__global__ void zero_kernel() {
    int t = blockIdx.x * blockDim.x + threadIdx.x;
    int stride = gridDim.x * blockDim.x;
    float4 z = make_float4(0.f, 0.f, 0.f, 0.f);
    float4* s1 = (float4*)d_S1;
    for (int i = t; i < N0 * 25 / 4; i += stride) s1[i] = z;
    float4* dg1 = (float4*)d_deg1;
    for (int i = t; i < N0 / 4; i += stride) dg1[i] = z;
    float4* a2 = (float4*)d_agg2;
    for (int i = t; i < N1 * 64 / 4; i += stride) a2[i] = z;
    float4* dg2 = (float4*)d_deg2;
    for (int i = t; i < N1 / 4; i += stride) dg2[i] = z;
    float4* f1 = (float4*)d_f1acc;
    for (int i = t; i < BATCH * 512 / 4; i += stride) f1[i] = z;
}

// ---------------- layer 1 scatter: 1 thread/edge, 4 tap atomics + deg ----------------
__global__ void edge1_kernel(const float* __restrict__ x,
                             const float2* __restrict__ pseudo,
                             const int* __restrict__ ei) {
    int e = blockIdx.x * 256 + threadIdx.x;
    if (e >= E0) return;
    float2 ps = __ldg(&pseudo[e]);
    float px = ps.x * (KTAP - 1), py = ps.y * (KTAP - 1);
    float kfx = floorf(px), kfy = floorf(py);
    float fx = px - kfx, fy = py - kfy;
    int k0x = (int)kfx, k0y = (int)kfy;
    int k1x = min(k0x + 1, KTAP - 1), k1y = min(k0y + 1, KTAP - 1);
    int src = __ldg(&ei[e]);
    int dst = __ldg(&ei[E0 + e]);
    float xs = __ldg(&x[src]);
    float* Sb = d_S1 + dst * 25;
    atomicAdd(Sb + k0x * 5 + k0y, (1.f - fx) * (1.f - fy) * xs);
    atomicAdd(Sb + k0x * 5 + k1y, (1.f - fx) * fy * xs);
    atomicAdd(Sb + k1x * 5 + k0y, fx * (1.f - fy) * xs);
    atomicAdd(Sb + k1x * 5 + k1y, fx * fy * xs);
    atomicAdd(&d_deg1[dst], 1.f);
}

// ---------------- fused layer-1 node update + ELU + 2x2 maxpool ----------------
__global__ void node1pool1_kernel(const float* __restrict__ x,
                                  const float* __restrict__ W1,
                                  const float* __restrict__ root1,
                                  const float* __restrict__ b1) {
    __shared__ unsigned long long sWp[25 * 16];   // W1 as f32x2 pairs
    __shared__ unsigned long long sRp[16];
    __shared__ unsigned long long sBp[16];
    int tid = threadIdx.x;                         // 256
    const unsigned long long* W1q = (const unsigned long long*)W1;
    for (int i = tid; i < 400; i += 256) sWp[i] = W1q[i];
    if (tid < 16) sRp[tid] = ((const unsigned long long*)root1)[tid];
    else if (tid < 32) sBp[tid - 16] = ((const unsigned long long*)b1)[tid - 16];
    __syncthreads();
    int gt = blockIdx.x * 256 + tid;
    int cell = gt >> 3;
    int sub = gt & 7;                              // channel quad index
    if (cell >= N1) return;
    int b = cell / 196, rem = cell % 196;
    int r2 = rem / 14, c2 = rem % 14;
    int base = b * 784 + r2 * 56 + c2 * 2;
    const int offs[4] = {0, 1, 28, 29};
    float pv0 = -1e30f, pv1 = -1e30f, pv2 = -1e30f, pv3 = -1e30f;
    float r0, r1, r2f, r3, bb0, bb1, bb2, bb3;
    unpack2(sRp[sub * 2], r0, r1);
    unpack2(sRp[sub * 2 + 1], r2f, r3);
    unpack2(sBp[sub * 2], bb0, bb1);
    unpack2(sBp[sub * 2 + 1], bb2, bb3);
    #pragma unroll
    for (int nn = 0; nn < 4; nn++) {
        int node = base + offs[nn];
        const float* Sb = d_S1 + node * 25;
        unsigned long long a0 = 0ull, a1 = 0ull;
        #pragma unroll
        for (int t = 0; t < 25; t++) {
            unsigned long long sp = pack2dup(__ldg(Sb + t));
            fma2(a0, sp, sWp[t * 16 + sub * 2]);
            fma2(a1, sp, sWp[t * 16 + sub * 2 + 1]);
        }
        float inv = 1.f / fmaxf(__ldg(&d_deg1[node]), 1.f);
        float xv = __ldg(&x[node]);
        float v0, v1, v2, v3;
        unpack2(a0, v0, v1);
        unpack2(a1, v2, v3);
        v0 = elu1(v0 * inv + xv * r0 + bb0);
        v1 = elu1(v1 * inv + xv * r1 + bb1);
        v2 = elu1(v2 * inv + xv * r2f + bb2);
        v3 = elu1(v3 * inv + xv * r3 + bb3);
        pv0 = fmaxf(pv0, v0);
        pv1 = fmaxf(pv1, v1);
        pv2 = fmaxf(pv2, v2);
        pv3 = fmaxf(pv3, v3);
    }
    ((float4*)(d_p1 + cell * 32))[sub] = make_float4(pv0, pv1, pv2, pv3);
}

// ---------------- y2 = P1[N1,32] @ W2mat[32,1600]  (tf32 tensor-core) ----------------
// grid = (25 taps, 154 m-blocks), 256 threads = 8 warps. Warp tile m16 x n64.
// Fragments per mma.m16n8k8: A row-major from sP, B col-from-[k][n] sW.
// sP stride 36 -> A-frag loads conflict-free; sW stride 72 -> B-frag conflict-free.
__global__ __launch_bounds__(256) void gemm_y2_kernel(const float* __restrict__ W2) {
    __shared__ unsigned int sP[128][36];   // tf32 bits of P tile [m][k]
    __shared__ unsigned int sW[32][72];    // tf32 bits of W tap [k][n]
    int tid = threadIdx.x;
    int kk = blockIdx.x;                   // tap
    int bm = blockIdx.y * 128;
    #pragma unroll
    for (int j = 0; j < 16; j++) {
        int i = tid + j * 256;
        int r = i >> 5, c = i & 31;
        int gm = bm + r;
        sP[r][c] = f2tf32((gm < N1) ? d_p1[gm * 32 + c] : 0.f);
    }
    #pragma unroll
    for (int j = 0; j < 8; j++) {
        int i = tid + j * 256;
        int k = i >> 6, n = i & 63;
        sW[k][n] = f2tf32(W2[kk * 2048 + i]);
    }
    __syncthreads();
    int wid = tid >> 5, lane = tid & 31;
    int g = lane >> 2, t = lane & 3;
    int wm = wid * 16;                      // warp's m-offset within tile
    // A fragments for the 4 k-steps (reused across all 8 n-tiles)
    unsigned int a[4][4];
    #pragma unroll
    for (int ks = 0; ks < 4; ks++) {
        a[ks][0] = sP[wm + g][ks * 8 + t];
        a[ks][1] = sP[wm + g + 8][ks * 8 + t];
        a[ks][2] = sP[wm + g][ks * 8 + t + 4];
        a[ks][3] = sP[wm + g + 8][ks * 8 + t + 4];
    }
    int row0 = bm + wm + g;
    int row1 = row0 + 8;
    #pragma unroll
    for (int nt = 0; nt < 8; nt++) {
        float c0 = 0.f, c1 = 0.f, c2 = 0.f, c3 = 0.f;
        #pragma unroll
        for (int ks = 0; ks < 4; ks++) {
            unsigned int b0 = sW[ks * 8 + t][nt * 8 + g];
            unsigned int b1 = sW[ks * 8 + t + 4][nt * 8 + g];
            mma_tf32(c0, c1, c2, c3, a[ks][0], a[ks][1], a[ks][2], a[ks][3], b0, b1);
        }
        int col = kk * 64 + nt * 8 + 2 * t;
        if (row0 < N1)
            *(float2*)(d_y2 + (size_t)row0 * 1600 + col) = make_float2(c0, c1);
        if (row1 < N1)
            *(float2*)(d_y2 + (size_t)row1 * 1600 + col) = make_float2(c2, c3);
    }
}

// ---------------- layer 2 scatter: gather 4 tap rows of y2, RED one 64-ch message ----------------
__global__ void edge2_kernel(const float2* __restrict__ pseudo,
                             const int* __restrict__ ei) {
    int sub = threadIdx.x & 15;
    int eloc = threadIdx.x >> 4;
    int e = blockIdx.x * 16 + eloc;
    if (e >= E1) return;
    float2 ps = __ldg(&pseudo[e]);
    float px = ps.x * (KTAP - 1), py = ps.y * (KTAP - 1);
    float kfx = floorf(px), kfy = floorf(py);
    float fx = px - kfx, fy = py - kfy;
    int k0x = (int)kfx, k0y = (int)kfy;
    int k1x = min(k0x + 1, KTAP - 1), k1y = min(k0y + 1, KTAP - 1);
    float w00 = (1.f - fx) * (1.f - fy);
    float w01 = (1.f - fx) * fy;
    float w10 = fx * (1.f - fy);
    float w11 = fx * fy;
    int src = __ldg(&ei[e]);
    int dst = __ldg(&ei[E1 + e]);
    const float* yb = d_y2 + (size_t)src * 1600;
    float4 v0 = __ldg(&((const float4*)(yb + (k0x * 5 + k0y) * 64))[sub]);
    float4 v1 = __ldg(&((const float4*)(yb + (k0x * 5 + k1y) * 64))[sub]);
    float4 v2 = __ldg(&((const float4*)(yb + (k1x * 5 + k0y) * 64))[sub]);
    float4 v3 = __ldg(&((const float4*)(yb + (k1x * 5 + k1y) * 64))[sub]);
    float4 m;
    m.x = w00 * v0.x + w01 * v1.x + w10 * v2.x + w11 * v3.x;
    m.y = w00 * v0.y + w01 * v1.y + w10 * v2.y + w11 * v3.y;
    m.z = w00 * v0.z + w01 * v1.z + w10 * v2.z + w11 * v3.z;
    m.w = w00 * v0.w + w01 * v1.w + w10 * v2.w + w11 * v3.w;
    red4(d_agg2 + dst * 64 + sub * 4, m);
    if (sub == 0) atomicAdd(&d_deg2[dst], 1.f);
}

// ---------------- layer 2 node: agg2/deg + p1@root2 + b2, ELU ----------------
__global__ __launch_bounds__(256) void node2_kernel(const float* __restrict__ root2,
                                                    const float* __restrict__ b2) {
    __shared__ __align__(16) float sR[32][64];
    __shared__ float sP[16][33];
    __shared__ float sdeg[16];
    int tid = threadIdx.x;
    int bn = blockIdx.x * 16;
    #pragma unroll
    for (int j = 0; j < 8; j++) {
        int i = tid + j * 256;
        ((float*)sR)[i] = root2[i];
    }
    #pragma unroll
    for (int j = 0; j < 2; j++) {
        int i = tid + j * 256;
        int r = i >> 5, c = i & 31;
        sP[r][c] = d_p1[(bn + r) * 32 + c];
    }
    if (tid < 16) sdeg[tid] = d_deg2[bn + tid];
    __syncthreads();
    int ty = tid >> 4, sub = tid & 15;
    unsigned long long a0 = 0ull, a1 = 0ull;
    #pragma unroll
    for (int i = 0; i < 32; i++) {
        unsigned long long ap = pack2dup(sP[ty][i]);
        ulonglong2 bv = *reinterpret_cast<const ulonglong2*>(&sR[i][sub * 4]);
        fma2(a0, ap, bv.x);
        fma2(a1, ap, bv.y);
    }
    int n = bn + ty;
    float inv = 1.f / fmaxf(sdeg[ty], 1.f);
    float r0, r1, r2, r3;
    unpack2(a0, r0, r1);
    unpack2(a1, r2, r3);
    float4 ag = *(const float4*)(d_agg2 + n * 64 + sub * 4);
    float4 bb = __ldg(&((const float4*)b2)[sub]);
    float4 o;
    o.x = elu1(ag.x * inv + r0 + bb.x);
    o.y = elu1(ag.y * inv + r1 + bb.y);
    o.z = elu1(ag.z * inv + r2 + bb.z);
    o.w = elu1(ag.w * inv + r3 + bb.w);
    *(float4*)(d_h2 + n * 64 + sub * 4) = o;
}

// ---------------- maxpool on [25,28,28,64] -> [25,14,14,64] (float4) ----------------
__global__ void pool2_kernel() {
    int idx = blockIdx.x * blockDim.x + threadIdx.x;
    if (idx >= NP2 * 16) return;
    int q = idx & 15;
    int m = idx >> 4;
    int c2 = m % 14, r2 = (m / 14) % 14, bb = m / 196;
    int base = (bb * 28 + r2 * 2) * 28 + c2 * 2;
    const float4* h = (const float4*)d_h2;
    float4 a0 = h[base * 16 + q];
    float4 a1 = h[(base + 1) * 16 + q];
    float4 a2 = h[(base + 28) * 16 + q];
    float4 a3 = h[(base + 29) * 16 + q];
    float4 r;
    r.x = fmaxf(fmaxf(a0.x, a1.x), fmaxf(a2.x, a3.x));
    r.y = fmaxf(fmaxf(a0.y, a1.y), fmaxf(a2.y, a3.y));
    r.z = fmaxf(fmaxf(a0.z, a1.z), fmaxf(a2.z, a3.z));
    r.w = fmaxf(fmaxf(a0.w, a1.w), fmaxf(a2.w, a3.w));
    ((float4*)d_pool2)[idx] = r;
}

// ---------------- fc1: [100,3136]@[3136,512], K split 4 ways, fp32x2, atomic combine ----------------
__global__ void fc1_kernel(const float* __restrict__ W) {
    __shared__ float sX[16][17];
    __shared__ __align__(16) float sW[16][64];
    int tid = threadIdx.x;
    int tx = tid & 15, ty = tid >> 4;
    int bn = blockIdx.x * 64;
    int bm = blockIdx.y * 16;
    int ks = blockIdx.z * 784;
    unsigned long long acc2[2] = {0ull, 0ull};
    for (int kc = 0; kc < 49; kc++) {
        int k0 = ks + kc * 16;
        {
            int gm = bm + ty;
            sX[ty][tx] = (gm < BATCH) ? d_pool2[gm * 3136 + k0 + tx] : 0.f;
        }
        #pragma unroll
        for (int j = 0; j < 4; j++) {
            int i = tid + j * 256;
            sW[i >> 6][i & 63] = W[(k0 + (i >> 6)) * 512 + bn + (i & 63)];
        }
        __syncthreads();
        #pragma unroll
        for (int k = 0; k < 16; k++) {
            unsigned long long ap = pack2dup(sX[ty][k]);
            ulonglong2 bv = *reinterpret_cast<const ulonglong2*>(&sW[k][tx * 4]);
            fma2(acc2[0], ap, bv.x);
            fma2(acc2[1], ap, bv.y);
        }
        __syncthreads();
    }
    int row = bm + ty;
    if (row < BATCH) {
        float a0, a1, a2, a3;
        unpack2(acc2[0], a0, a1);
        unpack2(acc2[1], a2, a3);
        float* p = &d_f1acc[row * 512 + bn + tx * 4];
        atomicAdd(p + 0, a0);
        atomicAdd(p + 1, a1);
        atomicAdd(p + 2, a2);
        atomicAdd(p + 3, a3);
    }
}

__global__ void elu_f1_kernel(const float* __restrict__ b) {
    int i = blockIdx.x * blockDim.x + threadIdx.x;
    if (i >= BATCH * 512) return;
    d_f1[i] = elu1(d_f1acc[i] + __ldg(&b[i & 511]));
}

// ---------------- fc2 + ELU + log_softmax ----------------
__global__ void fc2_kernel(const float* __restrict__ W,
                           const float* __restrict__ b,
                           float* __restrict__ out) {
    int row = blockIdx.x;
    int o = threadIdx.x >> 5;
    int lane = threadIdx.x & 31;
    float s = 0.f;
    for (int k = lane; k < 512; k += 32)
        s += d_f1[row * 512 + k] * __ldg(&W[k * 10 + o]);
    #pragma unroll
    for (int off = 16; off; off >>= 1) s += __shfl_xor_sync(0xffffffffu, s, off);
    __shared__ float vals[10];
    if (lane == 0) vals[o] = elu1(s + b[o]);
    __syncthreads();
    if (threadIdx.x == 0) {
        float mx = -1e30f;
        #pragma unroll
        for (int i = 0; i < 10; i++) mx = fmaxf(mx, vals[i]);
        float se = 0.f;
        #pragma unroll
        for (int i = 0; i < 10; i++) se += expf(vals[i] - mx);
        float lse = mx + logf(se);
        #pragma unroll
        for (int i = 0; i < 10; i++) out[row * 10 + i] = vals[i] - lse;
    }
}

extern "C" void kernel_launch(void* const* d_in, const int* in_sizes, int n_in,
                              void* d_out, int out_size) {
    const float* x        = (const float*)d_in[0];
    const float2* pseudo0 = (const float2*)d_in[1];
    const float2* pseudo1 = (const float2*)d_in[2];
    const float* W1       = (const float*)d_in[3];
    const float* root1    = (const float*)d_in[4];
    const float* b1       = (const float*)d_in[5];
    const float* W2       = (const float*)d_in[6];
    const float* root2    = (const float*)d_in[7];
    const float* b2       = (const float*)d_in[8];
    const float* fc1_w    = (const float*)d_in[9];
    const float* fc1_b    = (const float*)d_in[10];
    const float* fc2_w    = (const float*)d_in[11];
    const float* fc2_b    = (const float*)d_in[12];
    const int*   ei0      = (const int*)d_in[13];
    const int*   ei1      = (const int*)d_in[14];
    float* out = (float*)d_out;

    zero_kernel<<<512, 256>>>();
    edge1_kernel<<<(E0 + 255) / 256, 256>>>(x, pseudo0, ei0);
    node1pool1_kernel<<<(N1 * 8 + 255) / 256, 256>>>(x, W1, root1, b1);
    gemm_y2_kernel<<<dim3(25, (N1 + 127) / 128), 256>>>(W2);
    edge2_kernel<<<(E1 + 15) / 16, 256>>>(pseudo1, ei1);
    node2_kernel<<<N1 / 16, 256>>>(root2, b2);
    pool2_kernel<<<(NP2 * 16 + 255) / 256, 256>>>();
    fc1_kernel<<<dim3(8, 7, 4), 256>>>(fc1_w);
    elu_f1_kernel<<<(BATCH * 512 + 255) / 256, 256>>>(fc1_b);
    fc2_kernel<<<BATCH, 320>>>(fc2_w, fc2_b, out);
}

// round 14
// speedup vs baseline: 1.1875x; 1.0121x over previous
#include <cuda_runtime.h>
#include <cuda_bf16.h>
#include <math.h>

#define KTAP 5
#define N0 78400
#define E0 627200
#define N1 19600
#define E1 156800
#define NP2 4900
#define BATCH 100

// ---------------- scratch (static device globals; no allocation) ----------------
__device__ float d_S1[N0 * 25];        // per-dst tap scalar sums (layer 1)
__device__ float d_deg1[N0];
__device__ float d_p1[N1 * 32];
__device__ __nv_bfloat16 d_y2[N1 * 1600];   // y2[n, tap(25), ch(64)] in bf16 (62MB, L2-resident)
__device__ float d_agg2[N1 * 64];
__device__ float d_deg2[N1];
__device__ float d_h2[N1 * 64];
__device__ float d_pool2[NP2 * 64];    // == [100, 3136] for fc1
__device__ float d_f1acc[BATCH * 512];
__device__ float d_f1[BATCH * 512];

__device__ __forceinline__ float elu1(float v) { return v > 0.f ? v : expm1f(v); }

__device__ __forceinline__ void red4(float* p, float4 v) {
    asm volatile("red.global.add.v4.f32 [%0], {%1,%2,%3,%4};"
                 :: "l"(p), "f"(v.x), "f"(v.y), "f"(v.z), "f"(v.w) : "memory");
}

// ---- packed fp32x2 helpers ----
__device__ __forceinline__ unsigned long long pack2dup(float a) {
    unsigned long long r;
    asm("mov.b64 %0, {%1,%1};" : "=l"(r) : "f"(a));
    return r;
}
__device__ __forceinline__ void unpack2(unsigned long long v, float& lo, float& hi) {
    asm("mov.b64 {%0,%1}, %2;" : "=f"(lo), "=f"(hi) : "l"(v));
}
__device__ __forceinline__ void fma2(unsigned long long& d, unsigned long long a,
                                     unsigned long long b) {
    asm("fma.rn.f32x2 %0, %1, %2, %0;" : "+l"(d) : "l"(a), "l"(b));
}

// ---- tf32 helpers ----
__device__ __forceinline__ unsigned int f2tf32(float f) {
    unsigned int u;
    asm("cvt.rna.tf32.f32 %0, %1;" : "=r"(u) : "f"(f));
    return u;
}
__device__ __forceinline__ void mma_tf32(float& c0, float& c1, float& c2, float& c3,
                                         unsigned int a0, unsigned int a1,
                                         unsigned int a2, unsigned int a3,
                                         unsigned int b0, unsigned int b1) {
    asm("mma.sync.aligned.m16n8k8.row.col.f32.tf32.tf32.f32 "
        "{%0,%1,%2,%3}, {%4,%5,%6,%7}, {%8,%9}, {%0,%1,%2,%3};"
        : "+f"(c0), "+f"(c1), "+f"(c2), "+f"(c3)
        : "r"(a0), "r"(a1), "r"(a2), "r"(a3), "r"(b0), "r"(b1));
}

// ---------------- zeroing (fresh every replay; ~14MB total) ----------------
__global__ void zero_kernel() {
    int t = blockIdx.x * blockDim.x + threadIdx.x;
    int stride = gridDim.x * blockDim.x;
    float4 z = make_float4(0.f, 0.f, 0.f, 0.f);
    float4* s1 = (float4*)d_S1;
    for (int i = t; i < N0 * 25 / 4; i += stride) s1[i] = z;
    float4* dg1 = (float4*)d_deg1;
    for (int i = t; i < N0 / 4; i += stride) dg1[i] = z;
    float4* a2 = (float4*)d_agg2;
    for (int i = t; i < N1 * 64 / 4; i += stride) a2[i] = z;
    float4* dg2 = (float4*)d_deg2;
    for (int i = t; i < N1 / 4; i += stride) dg2[i] = z;
    float4* f1 = (float4*)d_f1acc;
    for (int i = t; i < BATCH * 512 / 4; i += stride) f1[i] = z;
}

// ---------------- layer 1 scatter: 1 thread/edge, 4 tap atomics + deg ----------------
__global__ void edge1_kernel(const float* __restrict__ x,
                             const float2* __restrict__ pseudo,
                             const int* __restrict__ ei) {
    int e = blockIdx.x * 256 + threadIdx.x;
    if (e >= E0) return;
    float2 ps = __ldg(&pseudo[e]);
    float px = ps.x * (KTAP - 1), py = ps.y * (KTAP - 1);
    float kfx = floorf(px), kfy = floorf(py);
    float fx = px - kfx, fy = py - kfy;
    int k0x = (int)kfx, k0y = (int)kfy;
    int k1x = min(k0x + 1, KTAP - 1), k1y = min(k0y + 1, KTAP - 1);
    int src = __ldg(&ei[e]);
    int dst = __ldg(&ei[E0 + e]);
    float xs = __ldg(&x[src]);
    float* Sb = d_S1 + dst * 25;
    atomicAdd(Sb + k0x * 5 + k0y, (1.f - fx) * (1.f - fy) * xs);
    atomicAdd(Sb + k0x * 5 + k1y, (1.f - fx) * fy * xs);
    atomicAdd(Sb + k1x * 5 + k0y, fx * (1.f - fy) * xs);
    atomicAdd(Sb + k1x * 5 + k1y, fx * fy * xs);
    atomicAdd(&d_deg1[dst], 1.f);
}

// ---------------- fused layer-1 node update + ELU + 2x2 maxpool ----------------
__global__ void node1pool1_kernel(const float* __restrict__ x,
                                  const float* __restrict__ W1,
                                  const float* __restrict__ root1,
                                  const float* __restrict__ b1) {
    __shared__ unsigned long long sWp[25 * 16];   // W1 as f32x2 pairs
    __shared__ unsigned long long sRp[16];
    __shared__ unsigned long long sBp[16];
    int tid = threadIdx.x;                         // 256
    const unsigned long long* W1q = (const unsigned long long*)W1;
    for (int i = tid; i < 400; i += 256) sWp[i] = W1q[i];
    if (tid < 16) sRp[tid] = ((const unsigned long long*)root1)[tid];
    else if (tid < 32) sBp[tid - 16] = ((const unsigned long long*)b1)[tid - 16];
    __syncthreads();
    int gt = blockIdx.x * 256 + tid;
    int cell = gt >> 3;
    int sub = gt & 7;                              // channel quad index
    if (cell >= N1) return;
    int b = cell / 196, rem = cell % 196;
    int r2 = rem / 14, c2 = rem % 14;
    int base = b * 784 + r2 * 56 + c2 * 2;
    const int offs[4] = {0, 1, 28, 29};
    float pv0 = -1e30f, pv1 = -1e30f, pv2 = -1e30f, pv3 = -1e30f;
    float r0, r1, r2f, r3, bb0, bb1, bb2, bb3;
    unpack2(sRp[sub * 2], r0, r1);
    unpack2(sRp[sub * 2 + 1], r2f, r3);
    unpack2(sBp[sub * 2], bb0, bb1);
    unpack2(sBp[sub * 2 + 1], bb2, bb3);
    #pragma unroll
    for (int nn = 0; nn < 4; nn++) {
        int node = base + offs[nn];
        const float* Sb = d_S1 + node * 25;
        unsigned long long a0 = 0ull, a1 = 0ull;
        #pragma unroll
        for (int t = 0; t < 25; t++) {
            unsigned long long sp = pack2dup(__ldg(Sb + t));
            fma2(a0, sp, sWp[t * 16 + sub * 2]);
            fma2(a1, sp, sWp[t * 16 + sub * 2 + 1]);
        }
        float inv = 1.f / fmaxf(__ldg(&d_deg1[node]), 1.f);
        float xv = __ldg(&x[node]);
        float v0, v1, v2, v3;
        unpack2(a0, v0, v1);
        unpack2(a1, v2, v3);
        v0 = elu1(v0 * inv + xv * r0 + bb0);
        v1 = elu1(v1 * inv + xv * r1 + bb1);
        v2 = elu1(v2 * inv + xv * r2f + bb2);
        v3 = elu1(v3 * inv + xv * r3 + bb3);
        pv0 = fmaxf(pv0, v0);
        pv1 = fmaxf(pv1, v1);
        pv2 = fmaxf(pv2, v2);
        pv3 = fmaxf(pv3, v3);
    }
    ((float4*)(d_p1 + cell * 32))[sub] = make_float4(pv0, pv1, pv2, pv3);
}

// ---------------- y2 = P1[N1,32] @ W2mat[32,1600]  (tf32 MMA, bf16 store) ----------------
// grid = (25 taps, 154 m-blocks), 256 threads = 8 warps. Warp tile m16 x n64.
__global__ __launch_bounds__(256) void gemm_y2_kernel(const float* __restrict__ W2) {
    __shared__ unsigned int sP[128][36];   // tf32 bits of P tile [m][k]
    __shared__ unsigned int sW[32][72];    // tf32 bits of W tap [k][n]
    int tid = threadIdx.x;
    int kk = blockIdx.x;                   // tap
    int bm = blockIdx.y * 128;
    #pragma unroll
    for (int j = 0; j < 16; j++) {
        int i = tid + j * 256;
        int r = i >> 5, c = i & 31;
        int gm = bm + r;
        sP[r][c] = f2tf32((gm < N1) ? d_p1[gm * 32 + c] : 0.f);
    }
    #pragma unroll
    for (int j = 0; j < 8; j++) {
        int i = tid + j * 256;
        int k = i >> 6, n = i & 63;
        sW[k][n] = f2tf32(W2[kk * 2048 + i]);
    }
    __syncthreads();
    int wid = tid >> 5, lane = tid & 31;
    int g = lane >> 2, t = lane & 3;
    int wm = wid * 16;                      // warp's m-offset within tile
    unsigned int a[4][4];
    #pragma unroll
    for (int ks = 0; ks < 4; ks++) {
        a[ks][0] = sP[wm + g][ks * 8 + t];
        a[ks][1] = sP[wm + g + 8][ks * 8 + t];
        a[ks][2] = sP[wm + g][ks * 8 + t + 4];
        a[ks][3] = sP[wm + g + 8][ks * 8 + t + 4];
    }
    int row0 = bm + wm + g;
    int row1 = row0 + 8;
    #pragma unroll
    for (int nt = 0; nt < 8; nt++) {
        float c0 = 0.f, c1 = 0.f, c2 = 0.f, c3 = 0.f;
        #pragma unroll
        for (int ks = 0; ks < 4; ks++) {
            unsigned int b0 = sW[ks * 8 + t][nt * 8 + g];
            unsigned int b1 = sW[ks * 8 + t + 4][nt * 8 + g];
            mma_tf32(c0, c1, c2, c3, a[ks][0], a[ks][1], a[ks][2], a[ks][3], b0, b1);
        }
        int col = kk * 64 + nt * 8 + 2 * t;
        if (row0 < N1) {
            __nv_bfloat162 p = __float22bfloat162_rn(make_float2(c0, c1));
            *(__nv_bfloat162*)(d_y2 + (size_t)row0 * 1600 + col) = p;
        }
        if (row1 < N1) {
            __nv_bfloat162 p = __float22bfloat162_rn(make_float2(c2, c3));
            *(__nv_bfloat162*)(d_y2 + (size_t)row1 * 1600 + col) = p;
        }
    }
}

// ---------------- layer 2 scatter: gather 4 bf16 tap rows of y2, RED one 64-ch message ----------------
// 16 lanes per edge; each lane owns a 4-channel quad (uint2 = 4 bf16)
__global__ void edge2_kernel(const float2* __restrict__ pseudo,
                             const int* __restrict__ ei) {
    int sub = threadIdx.x & 15;
    int eloc = threadIdx.x >> 4;
    int e = blockIdx.x * 16 + eloc;
    if (e >= E1) return;
    float2 ps = __ldg(&pseudo[e]);
    float px = ps.x * (KTAP - 1), py = ps.y * (KTAP - 1);
    float kfx = floorf(px), kfy = floorf(py);
    float fx = px - kfx, fy = py - kfy;
    int k0x = (int)kfx, k0y = (int)kfy;
    int k1x = min(k0x + 1, KTAP - 1), k1y = min(k0y + 1, KTAP - 1);
    float w00 = (1.f - fx) * (1.f - fy);
    float w01 = (1.f - fx) * fy;
    float w10 = fx * (1.f - fy);
    float w11 = fx * fy;
    int src = __ldg(&ei[e]);
    int dst = __ldg(&ei[E1 + e]);
    const __nv_bfloat16* yb = d_y2 + (size_t)src * 1600;
    const __nv_bfloat162* t0 = (const __nv_bfloat162*)(yb + (k0x * 5 + k0y) * 64) + sub * 2;
    const __nv_bfloat162* t1 = (const __nv_bfloat162*)(yb + (k0x * 5 + k1y) * 64) + sub * 2;
    const __nv_bfloat162* t2 = (const __nv_bfloat162*)(yb + (k1x * 5 + k0y) * 64) + sub * 2;
    const __nv_bfloat162* t3 = (const __nv_bfloat162*)(yb + (k1x * 5 + k1y) * 64) + sub * 2;
    float2 v0a = __bfloat1622float2(t0[0]), v0b = __bfloat1622float2(t0[1]);
    float2 v1a = __bfloat1622float2(t1[0]), v1b = __bfloat1622float2(t1[1]);
    float2 v2a = __bfloat1622float2(t2[0]), v2b = __bfloat1622float2(t2[1]);
    float2 v3a = __bfloat1622float2(t3[0]), v3b = __bfloat1622float2(t3[1]);
    float4 m;
    m.x = w00 * v0a.x + w01 * v1a.x + w10 * v2a.x + w11 * v3a.x;
    m.y = w00 * v0a.y + w01 * v1a.y + w10 * v2a.y + w11 * v3a.y;
    m.z = w00 * v0b.x + w01 * v1b.x + w10 * v2b.x + w11 * v3b.x;
    m.w = w00 * v0b.y + w01 * v1b.y + w10 * v2b.y + w11 * v3b.y;
    red4(d_agg2 + dst * 64 + sub * 4, m);
    if (sub == 0) atomicAdd(&d_deg2[dst], 1.f);
}

// ---------------- layer 2 node: agg2/deg + p1@root2 + b2, ELU ----------------
__global__ __launch_bounds__(256) void node2_kernel(const float* __restrict__ root2,
                                                    const float* __restrict__ b2) {
    __shared__ __align__(16) float sR[32][64];
    __shared__ float sP[16][33];
    __shared__ float sdeg[16];
    int tid = threadIdx.x;
    int bn = blockIdx.x * 16;
    #pragma unroll
    for (int j = 0; j < 8; j++) {
        int i = tid + j * 256;
        ((float*)sR)[i] = root2[i];
    }
    #pragma unroll
    for (int j = 0; j < 2; j++) {
        int i = tid + j * 256;
        int r = i >> 5, c = i & 31;
        sP[r][c] = d_p1[(bn + r) * 32 + c];
    }
    if (tid < 16) sdeg[tid] = d_deg2[bn + tid];
    __syncthreads();
    int ty = tid >> 4, sub = tid & 15;
    unsigned long long a0 = 0ull, a1 = 0ull;
    #pragma unroll
    for (int i = 0; i < 32; i++) {
        unsigned long long ap = pack2dup(sP[ty][i]);
        ulonglong2 bv = *reinterpret_cast<const ulonglong2*>(&sR[i][sub * 4]);
        fma2(a0, ap, bv.x);
        fma2(a1, ap, bv.y);
    }
    int n = bn + ty;
    float inv = 1.f / fmaxf(sdeg[ty], 1.f);
    float r0, r1, r2, r3;
    unpack2(a0, r0, r1);
    unpack2(a1, r2, r3);
    float4 ag = *(const float4*)(d_agg2 + n * 64 + sub * 4);
    float4 bb = __ldg(&((const float4*)b2)[sub]);
    float4 o;
    o.x = elu1(ag.x * inv + r0 + bb.x);
    o.y = elu1(ag.y * inv + r1 + bb.y);
    o.z = elu1(ag.z * inv + r2 + bb.z);
    o.w = elu1(ag.w * inv + r3 + bb.w);
    *(float4*)(d_h2 + n * 64 + sub * 4) = o;
}

// ---------------- maxpool on [25,28,28,64] -> [25,14,14,64] (float4) ----------------
__global__ void pool2_kernel() {
    int idx = blockIdx.x * blockDim.x + threadIdx.x;
    if (idx >= NP2 * 16) return;
    int q = idx & 15;
    int m = idx >> 4;
    int c2 = m % 14, r2 = (m / 14) % 14, bb = m / 196;
    int base = (bb * 28 + r2 * 2) * 28 + c2 * 2;
    const float4* h = (const float4*)d_h2;
    float4 a0 = h[base * 16 + q];
    float4 a1 = h[(base + 1) * 16 + q];
    float4 a2 = h[(base + 28) * 16 + q];
    float4 a3 = h[(base + 29) * 16 + q];
    float4 r;
    r.x = fmaxf(fmaxf(a0.x, a1.x), fmaxf(a2.x, a3.x));
    r.y = fmaxf(fmaxf(a0.y, a1.y), fmaxf(a2.y, a3.y));
    r.z = fmaxf(fmaxf(a0.z, a1.z), fmaxf(a2.z, a3.z));
    r.w = fmaxf(fmaxf(a0.w, a1.w), fmaxf(a2.w, a3.w));
    ((float4*)d_pool2)[idx] = r;
}

// ---------------- fc1: [100,3136]@[3136,512], K split 4 ways, fp32x2, atomic combine ----------------
__global__ void fc1_kernel(const float* __restrict__ W) {
    __shared__ float sX[16][17];
    __shared__ __align__(16) float sW[16][64];
    int tid = threadIdx.x;
    int tx = tid & 15, ty = tid >> 4;
    int bn = blockIdx.x * 64;
    int bm = blockIdx.y * 16;
    int ks = blockIdx.z * 784;
    unsigned long long acc2[2] = {0ull, 0ull};
    for (int kc = 0; kc < 49; kc++) {
        int k0 = ks + kc * 16;
        {
            int gm = bm + ty;
            sX[ty][tx] = (gm < BATCH) ? d_pool2[gm * 3136 + k0 + tx] : 0.f;
        }
        #pragma unroll
        for (int j = 0; j < 4; j++) {
            int i = tid + j * 256;
            sW[i >> 6][i & 63] = W[(k0 + (i >> 6)) * 512 + bn + (i & 63)];
        }
        __syncthreads();
        #pragma unroll
        for (int k = 0; k < 16; k++) {
            unsigned long long ap = pack2dup(sX[ty][k]);
            ulonglong2 bv = *reinterpret_cast<const ulonglong2*>(&sW[k][tx * 4]);
            fma2(acc2[0], ap, bv.x);
            fma2(acc2[1], ap, bv.y);
        }
        __syncthreads();
    }
    int row = bm + ty;
    if (row < BATCH) {
        float a0, a1, a2, a3;
        unpack2(acc2[0], a0, a1);
        unpack2(acc2[1], a2, a3);
        float* p = &d_f1acc[row * 512 + bn + tx * 4];
        atomicAdd(p + 0, a0);
        atomicAdd(p + 1, a1);
        atomicAdd(p + 2, a2);
        atomicAdd(p + 3, a3);
    }
}

__global__ void elu_f1_kernel(const float* __restrict__ b) {
    int i = blockIdx.x * blockDim.x + threadIdx.x;
    if (i >= BATCH * 512) return;
    d_f1[i] = elu1(d_f1acc[i] + __ldg(&b[i & 511]));
}

// ---------------- fc2 + ELU + log_softmax ----------------
__global__ void fc2_kernel(const float* __restrict__ W,
                           const float* __restrict__ b,
                           float* __restrict__ out) {
    int row = blockIdx.x;
    int o = threadIdx.x >> 5;
    int lane = threadIdx.x & 31;
    float s = 0.f;
    for (int k = lane; k < 512; k += 32)
        s += d_f1[row * 512 + k] * __ldg(&W[k * 10 + o]);
    #pragma unroll
    for (int off = 16; off; off >>= 1) s += __shfl_xor_sync(0xffffffffu, s, off);
    __shared__ float vals[10];
    if (lane == 0) vals[o] = elu1(s + b[o]);
    __syncthreads();
    if (threadIdx.x == 0) {
        float mx = -1e30f;
        #pragma unroll
        for (int i = 0; i < 10; i++) mx = fmaxf(mx, vals[i]);
        float se = 0.f;
        #pragma unroll
        for (int i = 0; i < 10; i++) se += expf(vals[i] - mx);
        float lse = mx + logf(se);
        #pragma unroll
        for (int i = 0; i < 10; i++) out[row * 10 + i] = vals[i] - lse;
    }
}

extern "C" void kernel_launch(void* const* d_in, const int* in_sizes, int n_in,
                              void* d_out, int out_size) {
    const float* x        = (const float*)d_in[0];
    const float2* pseudo0 = (const float2*)d_in[1];
    const float2* pseudo1 = (const float2*)d_in[2];
    const float* W1       = (const float*)d_in[3];
    const float* root1    = (const float*)d_in[4];
    const float* b1       = (const float*)d_in[5];
    const float* W2       = (const float*)d_in[6];
    const float* root2    = (const float*)d_in[7];
    const float* b2       = (const float*)d_in[8];
    const float* fc1_w    = (const float*)d_in[9];
    const float* fc1_b    = (const float*)d_in[10];
    const float* fc2_w    = (const float*)d_in[11];
    const float* fc2_b    = (const float*)d_in[12];
    const int*   ei0      = (const int*)d_in[13];
    const int*   ei1      = (const int*)d_in[14];
    float* out = (float*)d_out;

    zero_kernel<<<512, 256>>>();
    edge1_kernel<<<(E0 + 255) / 256, 256>>>(x, pseudo0, ei0);
    node1pool1_kernel<<<(N1 * 8 + 255) / 256, 256>>>(x, W1, root1, b1);
    gemm_y2_kernel<<<dim3(25, (N1 + 127) / 128), 256>>>(W2);
    edge2_kernel<<<(E1 + 15) / 16, 256>>>(pseudo1, ei1);
    node2_kernel<<<N1 / 16, 256>>>(root2, b2);
    pool2_kernel<<<(NP2 * 16 + 255) / 256, 256>>>();
    fc1_kernel<<<dim3(8, 7, 4), 256>>>(fc1_w);
    elu_f1_kernel<<<(BATCH * 512 + 255) / 256, 256>>>(fc1_b);
    fc2_kernel<<<BATCH, 320>>>(fc2_w, fc2_b, out);
}